// round 14
// baseline (speedup 1.0000x reference)
#include <cuda_runtime.h>
#include <math.h>
#include <stdint.h>

#define NN    50000
#define NE    800000
#define FIN   128
#define HID   32
#define HEADS 4
#define D1    128      // HEADS*HID
#define NCLS  16
#define MLPH  128
#define KMAX  16
#define NEG_SLOPE 0.2f
#define NBLK_SCAN 196  // ceil(NN/256)
#define NEG_INF  (-__int_as_float(0x7f800000))
#define SENT_LO  (-1e37f)

// ---------------- packed f32x2 helpers (sm_103 FFMA2 path) ----------------
__device__ __forceinline__ unsigned long long pack2(float x, float y) {
    unsigned long long r;
    asm("mov.b64 %0, {%1, %2};" : "=l"(r) : "f"(x), "f"(y));
    return r;
}
__device__ __forceinline__ void unpack2(unsigned long long v, float& x, float& y) {
    asm("mov.b64 {%0, %1}, %2;" : "=f"(x), "=f"(y) : "l"(v));
}
__device__ __forceinline__ unsigned long long fma2(unsigned long long a,
                                                   unsigned long long b,
                                                   unsigned long long c) {
    unsigned long long d;
    asm("fma.rn.f32x2 %0, %1, %2, %3;" : "=l"(d) : "l"(a), "l"(b), "l"(c));
    return d;
}

// ---------------- scratch (static device memory; no runtime allocs) ----------------
__device__ int   g_eid[NE];             // CSR position -> edge id (tie-break)
__device__ int   g_srcc[NE];            // CSR position -> src node
__device__ int   g_dstc[NE];            // CSR position -> dst node
__device__ int   g_counts[NN], g_offs[NN], g_cursor[NN];
__device__ int   g_blocksum[NBLK_SCAN], g_blockbase[NBLK_SCAN];
__device__ __align__(16) float g_xl1[(size_t)NN * D1];
__device__ __align__(16) float g_xr1[(size_t)NN * D1];
__device__ __align__(16) float g_scores1[(size_t)NE * HEADS];   // CSR order [pos][h]
__device__ __align__(16) float g_stats1[(size_t)NN * HEADS * 8];
__device__ __align__(16) float g_stats2[(size_t)NN * 8];
__device__ __align__(16) float g_h1[(size_t)NN * D1];
__device__ __align__(16) float g_noise1[(size_t)NN * D1];
__device__ __align__(16) float g_mlph[(size_t)NN * MLPH];
__device__ __align__(16) float g_n1[NN * NCLS];
__device__ __align__(16) float g_xl2[NN * NCLS];
__device__ __align__(16) float g_xr2[NN * NCLS];
__device__ __align__(16) float g_scores2[NE];
__device__ __align__(16) float g_out2[NN * NCLS];
__device__ __align__(16) float g_noise2[NN * NCLS];

// ---------------- CSR build ----------------
__global__ void init_csr_kernel() {
    int i = blockIdx.x * blockDim.x + threadIdx.x;
    if (i < NN) { g_counts[i] = 0; g_cursor[i] = 0; }
}

__global__ void count_kernel(const int* __restrict__ ei) {
    int e = blockIdx.x * blockDim.x + threadIdx.x;
    if (e < NE) {
        int d = min(max(ei[NE + e], 0), NN - 1);
        atomicAdd(&g_counts[d], 1);
    }
}

__global__ void block_sum_kernel() {
    __shared__ int sh[256];
    int b = blockIdx.x, t = threadIdx.x;
    int i = b * 256 + t;
    sh[t] = (i < NN) ? g_counts[i] : 0;
    __syncthreads();
    for (int o = 128; o > 0; o >>= 1) {
        if (t < o) sh[t] += sh[t + o];
        __syncthreads();
    }
    if (t == 0) g_blocksum[b] = sh[0];
}

__global__ void scan_partials_kernel() {
    __shared__ int sh[256];
    int t = threadIdx.x;
    int v = (t < NBLK_SCAN) ? g_blocksum[t] : 0;
    sh[t] = v;
    __syncthreads();
    for (int o = 1; o < 256; o <<= 1) {
        int u = (t >= o) ? sh[t - o] : 0;
        __syncthreads();
        sh[t] += u;
        __syncthreads();
    }
    if (t < NBLK_SCAN) g_blockbase[t] = sh[t] - v;
}

__global__ void scan_final_kernel() {
    __shared__ int sh[256];
    int b = blockIdx.x, t = threadIdx.x;
    int i = b * 256 + t;
    int v = (i < NN) ? g_counts[i] : 0;
    sh[t] = v;
    __syncthreads();
    for (int o = 1; o < 256; o <<= 1) {
        int u = (t >= o) ? sh[t - o] : 0;
        __syncthreads();
        sh[t] += u;
        __syncthreads();
    }
    if (i < NN) g_offs[i] = g_blockbase[b] + sh[t] - v;
}

__global__ void scatter_kernel(const int* __restrict__ ei) {
    int e = blockIdx.x * blockDim.x + threadIdx.x;
    if (e < NE) {
        int s = min(max(ei[e], 0), NN - 1);
        int d = min(max(ei[NE + e], 0), NN - 1);
        int pos = g_offs[d] + atomicAdd(&g_cursor[d], 1);
        g_eid[pos] = e;
        g_srcc[pos] = s;
        g_dstc[pos] = d;
    }
}

// ---------------- SGEMM: 128x128 tile, 8x8 microtile, FFMA2 inner loop ------------
__global__ void sgemm128_kernel(int tag, const float* __restrict__ Aparam,
                                const float* __restrict__ B1,
                                const float* __restrict__ B2,
                                const float* __restrict__ bias, int act) {
    const int M = NN, N = 128, K = 128;
    const int BK = 16;
    __shared__ float As[BK][128 + 4];
    __shared__ float Bs[BK][128];
    const float* A = (tag == 2) ? (const float*)g_noise1 : Aparam;
    const float* B = (tag == 0 && blockIdx.y == 1) ? B2 : B1;
    float* C = (tag == 2) ? g_mlph : (blockIdx.y == 0 ? g_xl1 : g_xr1);

    int row0 = blockIdx.x * 128;
    int tid = threadIdx.x;
    int tx = tid % 16, ty = tid / 16;
    int lr = tid / 16, lc = tid % 16;
    int bc = tid % 128, br0 = tid / 128;
    unsigned long long acc2[8][4];
#pragma unroll
    for (int i = 0; i < 8; i++)
#pragma unroll
        for (int j = 0; j < 4; j++) acc2[i][j] = 0ull;

    for (int k0 = 0; k0 < K; k0 += BK) {
#pragma unroll
        for (int i = 0; i < 8; i++) {
            int r = row0 + lr + 16 * i;
            float v = 0.f;
            if (r < M) v = A[(size_t)r * K + k0 + lc];
            As[lc][lr + 16 * i] = v;
        }
#pragma unroll
        for (int i = 0; i < 8; i++) {
            int kr = k0 + br0 + 2 * i;
            Bs[br0 + 2 * i][bc] = B[(size_t)kr * N + bc];
        }
        __syncthreads();
#pragma unroll
        for (int kk = 0; kk < BK; kk++) {
            float4 a0 = *(const float4*)&As[kk][ty * 8];
            float4 a1 = *(const float4*)&As[kk][ty * 8 + 4];
            float4 b0 = *(const float4*)&Bs[kk][tx * 8];
            float4 b1 = *(const float4*)&Bs[kk][tx * 8 + 4];
            unsigned long long bp[4];
            bp[0] = pack2(b0.x, b0.y);
            bp[1] = pack2(b0.z, b0.w);
            bp[2] = pack2(b1.x, b1.y);
            bp[3] = pack2(b1.z, b1.w);
            unsigned long long ap[8];
            ap[0] = pack2(a0.x, a0.x);
            ap[1] = pack2(a0.y, a0.y);
            ap[2] = pack2(a0.z, a0.z);
            ap[3] = pack2(a0.w, a0.w);
            ap[4] = pack2(a1.x, a1.x);
            ap[5] = pack2(a1.y, a1.y);
            ap[6] = pack2(a1.z, a1.z);
            ap[7] = pack2(a1.w, a1.w);
#pragma unroll
            for (int i = 0; i < 8; i++)
#pragma unroll
                for (int j = 0; j < 4; j++)
                    acc2[i][j] = fma2(ap[i], bp[j], acc2[i][j]);
        }
        __syncthreads();
    }
#pragma unroll
    for (int i = 0; i < 8; i++) {
        int r = row0 + ty * 8 + i;
        if (r >= M) continue;
#pragma unroll
        for (int j = 0; j < 4; j++) {
            float vlo, vhi;
            unpack2(acc2[i][j], vlo, vhi);
            int c = tx * 8 + j * 2;
            if (bias) { vlo += bias[c]; vhi += bias[c + 1]; }
            if (act == 1) {
                vlo = (vlo > 0.f) ? vlo : expm1f(vlo);
                vhi = (vhi > 0.f) ? vhi : expm1f(vhi);
            }
            C[(size_t)r * N + c]     = vlo;
            C[(size_t)r * N + c + 1] = vhi;
        }
    }
}

// N=16 GEMM (FFMA2 column pairs): g_n1 = g_mlph @ B + bias
// 256 threads = 32 rows x 8 column-pairs; thread owns cols (tx, tx+8).
__global__ void sgemm_n16_kernel(const float* __restrict__ B,
                                 const float* __restrict__ bias) {
    const int M = NN, K = 128;
    __shared__ float Bs[K * 16];
    __shared__ float As[32][K];
    int tid = threadIdx.x;
    int tx = tid % 8, ty = tid / 8;       // ty 0..31 rows, tx 0..7 pairs
    for (int i = tid; i < K * 16; i += 256) Bs[i] = B[i];
    int r = blockIdx.x * 32 + ty;
    // load 32 rows x 128 cols: each thread loads 16 elems of its row
#pragma unroll
    for (int i = 0; i < 16; i++) {
        int c = tx + 8 * i;
        As[ty][c] = (r < M) ? g_mlph[(size_t)r * K + c] : 0.f;
    }
    __syncthreads();
    unsigned long long acc = 0ull;
#pragma unroll 8
    for (int k = 0; k < K; k++) {
        float a = As[ty][k];
        acc = fma2(pack2(a, a), pack2(Bs[k * 16 + tx], Bs[k * 16 + tx + 8]), acc);
    }
    if (r < M) {
        float v0, v1;
        unpack2(acc, v0, v1);
        g_n1[(size_t)r * 16 + tx]     = v0 + bias[tx];
        g_n1[(size_t)r * 16 + tx + 8] = v1 + bias[tx + 8];
    }
}

// dual N=16 GEMM (FFMA2 l/r pairs): xl2 = h1 @ Wl2, xr2 = h1 @ Wr2
__global__ void sgemm_n16_dual_kernel(const float* __restrict__ Bl,
                                      const float* __restrict__ Br) {
    const int M = NN, K = 128;
    __shared__ float Bsl[K * 16];
    __shared__ float Bsr[K * 16];
    __shared__ float As[16][K];
    int tid = threadIdx.x;
    int tx = tid % 16, ty = tid / 16;
    for (int i = tid; i < K * 16; i += 256) { Bsl[i] = Bl[i]; Bsr[i] = Br[i]; }
    int r = blockIdx.x * 16 + ty;
#pragma unroll
    for (int i = 0; i < 8; i++) {
        int c = tx + 16 * i;
        As[ty][c] = (r < M) ? g_h1[(size_t)r * K + c] : 0.f;
    }
    __syncthreads();
    unsigned long long acc = 0ull;   // {accl, accr}
#pragma unroll 8
    for (int k = 0; k < K; k++) {
        float a = As[ty][k];
        acc = fma2(pack2(a, a), pack2(Bsl[k * 16 + tx], Bsr[k * 16 + tx]), acc);
    }
    if (r < M) {
        float vl, vr;
        unpack2(acc, vl, vr);
        g_xl2[(size_t)r * 16 + tx] = vl;
        g_xr2[(size_t)r * 16 + tx] = vr;
    }
}

// ---------------- edge scores layer 1: warp per CSR position ----------------------
__global__ void edge_scores1_kernel(const float* __restrict__ att) {
    int w = blockIdx.x * (blockDim.x >> 5) + (threadIdx.x >> 5);
    if (w >= NE) return;
    int lane = threadIdx.x & 31;
    int s = g_srcc[w], d = g_dstc[w];
    float4 a = *(const float4*)(g_xl1 + (size_t)s * D1 + lane * 4);
    float4 b = *(const float4*)(g_xr1 + (size_t)d * D1 + lane * 4);
    float4 t = __ldg((const float4*)att + lane);
    float vx = a.x + b.x; vx = (vx > 0.f) ? vx : NEG_SLOPE * vx;
    float vy = a.y + b.y; vy = (vy > 0.f) ? vy : NEG_SLOPE * vy;
    float vz = a.z + b.z; vz = (vz > 0.f) ? vz : NEG_SLOPE * vz;
    float vw = a.w + b.w; vw = (vw > 0.f) ? vw : NEG_SLOPE * vw;
    float p = vx * t.x + vy * t.y + vz * t.z + vw * t.w;
    p += __shfl_xor_sync(0xffffffffu, p, 1);
    p += __shfl_xor_sync(0xffffffffu, p, 2);
    p += __shfl_xor_sync(0xffffffffu, p, 4);
    if ((lane & 7) == 0) g_scores1[(size_t)w * HEADS + (lane >> 3)] = p;
}

// ---------------- edge scores layer 2: warp handles 8 CSR positions ---------------
__global__ void edge_scores2_kernel(const float* __restrict__ att) {
    int w = blockIdx.x * (blockDim.x >> 5) + (threadIdx.x >> 5);
    int lane = threadIdx.x & 31;
    int sub = lane >> 2;
    int i = lane & 3;
    int e = w * 8 + sub;
    float p = 0.f;
    if (e < NE) {
        int s = g_srcc[e], d = g_dstc[e];
        float4 a = *(const float4*)(g_xl2 + (size_t)s * NCLS + i * 4);
        float4 b = *(const float4*)(g_xr2 + (size_t)d * NCLS + i * 4);
        float4 t = __ldg((const float4*)att + i);
        float vx = a.x + b.x; vx = (vx > 0.f) ? vx : NEG_SLOPE * vx;
        float vy = a.y + b.y; vy = (vy > 0.f) ? vy : NEG_SLOPE * vy;
        float vz = a.z + b.z; vz = (vz > 0.f) ? vz : NEG_SLOPE * vz;
        float vw = a.w + b.w; vw = (vw > 0.f) ? vw : NEG_SLOPE * vw;
        p = vx * t.x + vy * t.y + vz * t.z + vw * t.w;
    }
    p += __shfl_xor_sync(0xffffffffu, p, 1);
    p += __shfl_xor_sync(0xffffffffu, p, 2);
    if (i == 0 && e < NE) g_scores2[e] = p;
}

// ---------------- top-k stats: branchless register list, single pass --------------
template <int KM>
__device__ __forceinline__ void topk_core(const float* __restrict__ scores,
                                          float* __restrict__ stats,
                                          int H, int h, int t, int beg, int cnt, int k) {
    float ts[KM];
    int   te[KM];
#pragma unroll
    for (int i = 0; i < KM; i++) { ts[i] = NEG_INF; te[i] = 0x7fffffff; }

    float mn = NEG_INF;   // online noise max
    float sn = 0.f;       // online noise sum (ref mn)

    for (int p = 0; p < cnt; p++) {
        int idx = beg + p;
        float s = scores[(size_t)idx * H + h];
        int e = g_eid[idx];
        bool beats_tail = (s > ts[KM - 1]) || (s == ts[KM - 1] && e < te[KM - 1]);
        float rej;
        if (beats_tail) {
            rej = ts[KM - 1];
            bool nb[KM];
#pragma unroll
            for (int i = 0; i < KM; i++)
                nb[i] = (s > ts[i]) || (s == ts[i] && e < te[i]);
#pragma unroll
            for (int i = KM - 1; i >= 1; i--)
                if (nb[i - 1]) { ts[i] = ts[i - 1]; te[i] = te[i - 1]; }
#pragma unroll
            for (int i = 0; i < KM; i++) {
                bool ins = nb[i] && (i == 0 || !nb[i - 1]);
                if (ins) { ts[i] = s; te[i] = e; }
            }
        } else {
            rej = s;
        }
        if (rej > SENT_LO) {
            if (rej <= mn) sn += __expf(rej - mn);
            else { sn = sn * __expf(mn - rej) + 1.f; mn = rej; }
        }
    }

    int m = min(cnt, KM);
#pragma unroll
    for (int i = 0; i < KM; i++) {
        if (i >= k && i < m && ts[i] > SENT_LO) {
            float v = ts[i];
            if (v <= mn) sn += __expf(v - mn);
            else { sn = sn * __expf(mn - v) + 1.f; mn = v; }
        }
    }

    bool all_kept = (cnt <= k);
    float thr_s = __int_as_float(0x7f800000);
    int   thr_e = -1;
#pragma unroll
    for (int i = 0; i < KM; i++)
        if (i == k - 1) { thr_s = ts[i]; thr_e = te[i]; }

    float mk = (k > 0) ? ts[0] : 0.f;
    float sumk = 0.f;
#pragma unroll
    for (int i = 0; i < KM; i++)
        if (i < k && ts[i] > SENT_LO) sumk += __expf(ts[i] - mk);

    if (mn <= SENT_LO) mn = 0.f;
    float invk = 1.f / (sumk + 1e-16f);
    float invn = 1.f / (sn + 1e-16f);

    float4 s0 = make_float4(thr_s, __int_as_float(thr_e), mk, invk);
    float4 s1 = make_float4(mn, invn, all_kept ? 1.f : 0.f, 0.f);
    *(float4*)&stats[(size_t)t * 8]     = s0;
    *(float4*)&stats[(size_t)t * 8 + 4] = s1;
}

__global__ void topk_stats_kernel(int layer, const int* __restrict__ kptr) {
    const int H = (layer == 1) ? HEADS : 1;
    const float* scores = (layer == 1) ? (const float*)g_scores1 : (const float*)g_scores2;
    float* stats = (layer == 1) ? g_stats1 : g_stats2;

    int t = blockIdx.x * blockDim.x + threadIdx.x;
    if (t >= NN * H) return;
    int n = t / H, h = t - n * H;
    int beg = g_offs[n], cnt = g_counts[n];
    if (cnt == 0) return;
    int k = *kptr;
    k = min(max(k, 0), KMAX);

    if (k <= 8) topk_core<8>(scores, stats, H, h, t, beg, cnt, k);
    else        topk_core<16>(scores, stats, H, h, t, beg, cnt, k);
}

// ---------------- aggregation layer 1: warp per (node, head) ----------------------
__global__ void aggregate1_kernel(const float* __restrict__ b1) {
    int w = blockIdx.x * (blockDim.x >> 5) + (threadIdx.x >> 5);
    if (w >= NN * HEADS) return;
    int lane = threadIdx.x & 31;
    int n = w >> 2, h = w & 3;
    int beg = g_offs[n], cnt = g_counts[n];
    float acc = 0.f, accn = 0.f;
    if (cnt > 0) {
        float4 s0 = *(const float4*)&g_stats1[(size_t)w * 8];
        float4 s1 = *(const float4*)&g_stats1[(size_t)w * 8 + 4];
        float thr_s = s0.x, mk = s0.z, invk = s0.w, mn = s1.x, invn = s1.y;
        int thr_e = __float_as_int(s0.y);
        bool all_kept = (s1.z != 0.f);
        for (int p0 = 0; p0 < cnt; p0 += 32) {
            int p = p0 + lane;
            float a = 0.f, an = 0.f;
            int src = 0;
            if (p < cnt) {
                int idx = beg + p;
                float s = g_scores1[(size_t)idx * HEADS + h];
                int e = g_eid[idx];
                src = g_srcc[idx];
                bool kept = all_kept || (s > thr_s) || (s == thr_s && e <= thr_e);
                float ex = __expf(s - (kept ? mk : mn));
                a  = kept ? ex * invk : 0.f;
                an = kept ? 0.f : ex * invn;
            }
            int lim = min(32, cnt - p0);
            for (int j = 0; j < lim; j++) {
                float aj  = __shfl_sync(0xffffffffu, a, j);
                float anj = __shfl_sync(0xffffffffu, an, j);
                int   sj  = __shfl_sync(0xffffffffu, src, j);
                float xv = g_xl1[(size_t)sj * D1 + h * 32 + lane];
                acc  += aj * xv;
                accn += anj * xv;
            }
        }
    }
    int c = h * 32 + lane;
    float bb = b1[c];
    float o = acc + bb;
    g_h1[(size_t)n * D1 + c]     = (o > 0.f) ? o : expm1f(o);
    g_noise1[(size_t)n * D1 + c] = accn + bb;
}

// ---------------- aggregation layer 2: half-warp per node, lane = class ------------
__global__ void aggregate2_kernel(const float* __restrict__ b2) {
    int w = blockIdx.x * (blockDim.x >> 5) + (threadIdx.x >> 5);
    int lane = threadIdx.x & 31;
    int sub = lane >> 4;
    int c = lane & 15;
    int n = w * 2 + sub;
    if (n >= NN) return;
    int beg = g_offs[n], cnt = g_counts[n];
    float acc = 0.f, accn = 0.f;
    if (cnt > 0) {
        float4 s0 = *(const float4*)&g_stats2[(size_t)n * 8];
        float4 s1 = *(const float4*)&g_stats2[(size_t)n * 8 + 4];
        float thr_s = s0.x, mk = s0.z, invk = s0.w, mn = s1.x, invn = s1.y;
        int thr_e = __float_as_int(s0.y);
        bool all_kept = (s1.z != 0.f);
        for (int p0 = 0; p0 < cnt; p0 += 16) {
            int p = p0 + c;
            float a = 0.f, an = 0.f;
            int src = 0;
            if (p < cnt) {
                int idx = beg + p;
                float s = g_scores2[idx];
                int e = g_eid[idx];
                src = g_srcc[idx];
                bool kept = all_kept || (s > thr_s) || (s == thr_s && e <= thr_e);
                float ex = __expf(s - (kept ? mk : mn));
                a  = kept ? ex * invk : 0.f;
                an = kept ? 0.f : ex * invn;
            }
            int lim = min(16, cnt - p0);
            int base = sub << 4;
            for (int j = 0; j < lim; j++) {
                float aj  = __shfl_sync(0xffffffffu, a, base + j);
                float anj = __shfl_sync(0xffffffffu, an, base + j);
                int   sj  = __shfl_sync(0xffffffffu, src, base + j);
                float xv = g_xl2[(size_t)sj * NCLS + c];
                acc  += aj * xv;
                accn += anj * xv;
            }
        }
    }
    float bb = b2[c];
    g_out2[(size_t)n * NCLS + c]   = acc + bb;
    g_noise2[(size_t)n * NCLS + c] = accn + bb;
}

// ---------------- log_softmax over 16 classes, thread per row, 3 inputs ------------
__global__ void log_softmax16_kernel(float* __restrict__ out) {
    int r = blockIdx.x * blockDim.x + threadIdx.x;
    if (r >= 3 * NN) return;
    const float* in = (r < NN) ? (const float*)g_out2
                    : (r < 2 * NN) ? (const float*)g_n1 - (size_t)NN * NCLS
                    : (const float*)g_noise2 - 2 * (size_t)NN * NCLS;
    float v[NCLS];
    float mx = -3.4e38f;
#pragma unroll
    for (int c = 0; c < NCLS; c++) { v[c] = in[(size_t)r * NCLS + c]; mx = fmaxf(mx, v[c]); }
    float s = 0.f;
#pragma unroll
    for (int c = 0; c < NCLS; c++) s += __expf(v[c] - mx);
    float ls = mx + __logf(s);
#pragma unroll
    for (int c = 0; c < NCLS; c++) out[(size_t)r * NCLS + c] = v[c] - ls;
}

// ---------------- host ----------------
extern "C" void kernel_launch(void* const* d_in, const int* in_sizes, int n_in,
                              void* d_out, int out_size) {
    const float* x      = (const float*)d_in[0];
    const int*   ei     = (const int*)d_in[1];
    const int*   kptr   = (const int*)d_in[2];
    const float* Wl1    = (const float*)d_in[3];
    const float* Wr1    = (const float*)d_in[4];
    const float* att1   = (const float*)d_in[5];
    const float* b1     = (const float*)d_in[6];
    const float* Wl2    = (const float*)d_in[7];
    const float* Wr2    = (const float*)d_in[8];
    const float* att2   = (const float*)d_in[9];
    const float* b2     = (const float*)d_in[10];
    const float* lin1_w = (const float*)d_in[11];
    const float* lin1_b = (const float*)d_in[12];
    const float* lin2_w = (const float*)d_in[13];
    const float* lin2_b = (const float*)d_in[14];
    float* out = (float*)d_out;

    dim3 gProj((NN + 127) / 128, 2);

    // --- CSR build interleaved with projections (slot #4 = sgemm128 for ncu) ---
    init_csr_kernel<<<(NN + 255) / 256, 256>>>();                 // 1
    count_kernel<<<(NE + 255) / 256, 256>>>(ei);                  // 2
    block_sum_kernel<<<NBLK_SCAN, 256>>>();                       // 3
    sgemm128_kernel<<<gProj, 256>>>(0, x, Wl1, Wr1, nullptr, 0);  // 4 (profiled)
    scan_partials_kernel<<<1, 256>>>();                           // 5
    scan_final_kernel<<<NBLK_SCAN, 256>>>();                      // 6
    scatter_kernel<<<(NE + 255) / 256, 256>>>(ei);                // 7

    // --- layer 1 attention ---
    edge_scores1_kernel<<<(NE + 7) / 8, 256>>>(att1);
    topk_stats_kernel<<<(NN * HEADS + 255) / 256, 256>>>(1, kptr);
    aggregate1_kernel<<<(NN * HEADS + 7) / 8, 256>>>(b1);

    // --- noise MLP ---
    dim3 gMlp((NN + 127) / 128, 1);
    sgemm128_kernel<<<gMlp, 256>>>(2, nullptr, lin1_w, nullptr, lin1_b, 1);
    sgemm_n16_kernel<<<(NN + 31) / 32, 256>>>(lin2_w, lin2_b);

    // --- layer 2 projections ---
    sgemm_n16_dual_kernel<<<(NN + 15) / 16, 256>>>(Wl2, Wr2);

    // --- layer 2 attention ---
    edge_scores2_kernel<<<((NE + 7) / 8 + 7) / 8, 256>>>(att2);
    topk_stats_kernel<<<(NN + 255) / 256, 256>>>(2, kptr);
    aggregate2_kernel<<<((NN + 1) / 2 + 7) / 8, 256>>>(b2);

    // --- outputs ---
    log_softmax16_kernel<<<(3 * NN + 255) / 256, 256>>>(out);
}

// round 15
// speedup vs baseline: 1.0700x; 1.0700x over previous
#include <cuda_runtime.h>
#include <math.h>
#include <stdint.h>

#define NN    50000
#define NE    800000
#define FIN   128
#define HID   32
#define HEADS 4
#define D1    128      // HEADS*HID
#define NCLS  16
#define MLPH  128
#define KMAX  16
#define NEG_SLOPE 0.2f
#define NBLK_SCAN 196  // ceil(NN/256)
#define NEG_INF  (-__int_as_float(0x7f800000))
#define SENT_LO  (-1e37f)

// ---------------- packed f32x2 helpers (sm_103 FFMA2 path) ----------------
__device__ __forceinline__ unsigned long long pack2(float x, float y) {
    unsigned long long r;
    asm("mov.b64 %0, {%1, %2};" : "=l"(r) : "f"(x), "f"(y));
    return r;
}
__device__ __forceinline__ void unpack2(unsigned long long v, float& x, float& y) {
    asm("mov.b64 {%0, %1}, %2;" : "=f"(x), "=f"(y) : "l"(v));
}
__device__ __forceinline__ unsigned long long fma2(unsigned long long a,
                                                   unsigned long long b,
                                                   unsigned long long c) {
    unsigned long long d;
    asm("fma.rn.f32x2 %0, %1, %2, %3;" : "=l"(d) : "l"(a), "l"(b), "l"(c));
    return d;
}

// ---------------- scratch (static device memory; no runtime allocs) ----------------
__device__ int   g_eid[NE];             // CSR position -> edge id (tie-break)
__device__ int   g_srcc[NE];            // CSR position -> src node
__device__ int   g_dstc[NE];            // CSR position -> dst node
__device__ int   g_counts[NN], g_offs[NN], g_cursor[NN];
__device__ int   g_blocksum[NBLK_SCAN], g_blockbase[NBLK_SCAN];
__device__ __align__(16) float g_xl1[(size_t)NN * D1];
__device__ __align__(16) float g_xr1[(size_t)NN * D1];
__device__ __align__(16) float g_scores1[(size_t)NE * HEADS];   // CSR order [pos][h]
__device__ __align__(16) float g_stats1[(size_t)NN * HEADS * 8];
__device__ __align__(16) float g_stats2[(size_t)NN * 8];
__device__ __align__(16) float g_h1[(size_t)NN * D1];
__device__ __align__(16) float g_noise1[(size_t)NN * D1];
__device__ __align__(16) float g_mlph[(size_t)NN * MLPH];
__device__ __align__(16) float g_n1[NN * NCLS];
__device__ __align__(16) float g_xl2[NN * NCLS];
__device__ __align__(16) float g_xr2[NN * NCLS];
__device__ __align__(16) float g_scores2[NE];
__device__ __align__(16) float g_out2[NN * NCLS];
__device__ __align__(16) float g_noise2[NN * NCLS];

// ---------------- CSR build ----------------
__global__ void init_csr_kernel() {
    int i = blockIdx.x * blockDim.x + threadIdx.x;
    if (i < NN) { g_counts[i] = 0; g_cursor[i] = 0; }
}

__global__ void count_kernel(const int* __restrict__ ei) {
    int e = blockIdx.x * blockDim.x + threadIdx.x;
    if (e < NE) {
        int d = min(max(ei[NE + e], 0), NN - 1);
        atomicAdd(&g_counts[d], 1);
    }
}

__global__ void block_sum_kernel() {
    __shared__ int sh[256];
    int b = blockIdx.x, t = threadIdx.x;
    int i = b * 256 + t;
    sh[t] = (i < NN) ? g_counts[i] : 0;
    __syncthreads();
    for (int o = 128; o > 0; o >>= 1) {
        if (t < o) sh[t] += sh[t + o];
        __syncthreads();
    }
    if (t == 0) g_blocksum[b] = sh[0];
}

__global__ void scan_partials_kernel() {
    __shared__ int sh[256];
    int t = threadIdx.x;
    int v = (t < NBLK_SCAN) ? g_blocksum[t] : 0;
    sh[t] = v;
    __syncthreads();
    for (int o = 1; o < 256; o <<= 1) {
        int u = (t >= o) ? sh[t - o] : 0;
        __syncthreads();
        sh[t] += u;
        __syncthreads();
    }
    if (t < NBLK_SCAN) g_blockbase[t] = sh[t] - v;
}

__global__ void scan_final_kernel() {
    __shared__ int sh[256];
    int b = blockIdx.x, t = threadIdx.x;
    int i = b * 256 + t;
    int v = (i < NN) ? g_counts[i] : 0;
    sh[t] = v;
    __syncthreads();
    for (int o = 1; o < 256; o <<= 1) {
        int u = (t >= o) ? sh[t - o] : 0;
        __syncthreads();
        sh[t] += u;
        __syncthreads();
    }
    if (i < NN) g_offs[i] = g_blockbase[b] + sh[t] - v;
}

__global__ void scatter_kernel(const int* __restrict__ ei) {
    int e = blockIdx.x * blockDim.x + threadIdx.x;
    if (e < NE) {
        int s = min(max(ei[e], 0), NN - 1);
        int d = min(max(ei[NE + e], 0), NN - 1);
        int pos = g_offs[d] + atomicAdd(&g_cursor[d], 1);
        g_eid[pos] = e;
        g_srcc[pos] = s;
        g_dstc[pos] = d;
    }
}

// ---------------- SGEMM: 128x128 tile, 8x8 microtile, FFMA2 inner loop ------------
__global__ void sgemm128_kernel(int tag, const float* __restrict__ Aparam,
                                const float* __restrict__ B1,
                                const float* __restrict__ B2,
                                const float* __restrict__ bias, int act) {
    const int M = NN, N = 128, K = 128;
    const int BK = 16;
    __shared__ float As[BK][128 + 4];
    __shared__ float Bs[BK][128];
    const float* A = (tag == 2) ? (const float*)g_noise1 : Aparam;
    const float* B = (tag == 0 && blockIdx.y == 1) ? B2 : B1;
    float* C = (tag == 2) ? g_mlph : (blockIdx.y == 0 ? g_xl1 : g_xr1);

    int row0 = blockIdx.x * 128;
    int tid = threadIdx.x;
    int tx = tid % 16, ty = tid / 16;
    int lr = tid / 16, lc = tid % 16;
    int bc = tid % 128, br0 = tid / 128;
    unsigned long long acc2[8][4];
#pragma unroll
    for (int i = 0; i < 8; i++)
#pragma unroll
        for (int j = 0; j < 4; j++) acc2[i][j] = 0ull;

    for (int k0 = 0; k0 < K; k0 += BK) {
#pragma unroll
        for (int i = 0; i < 8; i++) {
            int r = row0 + lr + 16 * i;
            float v = 0.f;
            if (r < M) v = A[(size_t)r * K + k0 + lc];
            As[lc][lr + 16 * i] = v;
        }
#pragma unroll
        for (int i = 0; i < 8; i++) {
            int kr = k0 + br0 + 2 * i;
            Bs[br0 + 2 * i][bc] = B[(size_t)kr * N + bc];
        }
        __syncthreads();
#pragma unroll
        for (int kk = 0; kk < BK; kk++) {
            float4 a0 = *(const float4*)&As[kk][ty * 8];
            float4 a1 = *(const float4*)&As[kk][ty * 8 + 4];
            float4 b0 = *(const float4*)&Bs[kk][tx * 8];
            float4 b1 = *(const float4*)&Bs[kk][tx * 8 + 4];
            unsigned long long bp[4];
            bp[0] = pack2(b0.x, b0.y);
            bp[1] = pack2(b0.z, b0.w);
            bp[2] = pack2(b1.x, b1.y);
            bp[3] = pack2(b1.z, b1.w);
            unsigned long long ap[8];
            ap[0] = pack2(a0.x, a0.x);
            ap[1] = pack2(a0.y, a0.y);
            ap[2] = pack2(a0.z, a0.z);
            ap[3] = pack2(a0.w, a0.w);
            ap[4] = pack2(a1.x, a1.x);
            ap[5] = pack2(a1.y, a1.y);
            ap[6] = pack2(a1.z, a1.z);
            ap[7] = pack2(a1.w, a1.w);
#pragma unroll
            for (int i = 0; i < 8; i++)
#pragma unroll
                for (int j = 0; j < 4; j++)
                    acc2[i][j] = fma2(ap[i], bp[j], acc2[i][j]);
        }
        __syncthreads();
    }
#pragma unroll
    for (int i = 0; i < 8; i++) {
        int r = row0 + ty * 8 + i;
        if (r >= M) continue;
#pragma unroll
        for (int j = 0; j < 4; j++) {
            float vlo, vhi;
            unpack2(acc2[i][j], vlo, vhi);
            int c = tx * 8 + j * 2;
            if (bias) { vlo += bias[c]; vhi += bias[c + 1]; }
            if (act == 1) {
                vlo = (vlo > 0.f) ? vlo : expm1f(vlo);
                vhi = (vhi > 0.f) ? vhi : expm1f(vhi);
            }
            C[(size_t)r * N + c]     = vlo;
            C[(size_t)r * N + c + 1] = vhi;
        }
    }
}

// N=16 GEMM (FFMA2 column pairs): g_n1 = g_mlph @ B + bias
__global__ void sgemm_n16_kernel(const float* __restrict__ B,
                                 const float* __restrict__ bias) {
    const int M = NN, K = 128;
    __shared__ float Bs[K * 16];
    __shared__ float As[32][K];
    int tid = threadIdx.x;
    int tx = tid % 8, ty = tid / 8;       // ty 0..31 rows, tx 0..7 pairs
    for (int i = tid; i < K * 16; i += 256) Bs[i] = B[i];
    int r = blockIdx.x * 32 + ty;
#pragma unroll
    for (int i = 0; i < 16; i++) {
        int c = tx + 8 * i;
        As[ty][c] = (r < M) ? g_mlph[(size_t)r * K + c] : 0.f;
    }
    __syncthreads();
    unsigned long long acc = 0ull;
#pragma unroll 8
    for (int k = 0; k < K; k++) {
        float a = As[ty][k];
        acc = fma2(pack2(a, a), pack2(Bs[k * 16 + tx], Bs[k * 16 + tx + 8]), acc);
    }
    if (r < M) {
        float v0, v1;
        unpack2(acc, v0, v1);
        g_n1[(size_t)r * 16 + tx]     = v0 + bias[tx];
        g_n1[(size_t)r * 16 + tx + 8] = v1 + bias[tx + 8];
    }
}

// dual N=16 GEMM (FFMA2 l/r pairs): xl2 = h1 @ Wl2, xr2 = h1 @ Wr2
__global__ void sgemm_n16_dual_kernel(const float* __restrict__ Bl,
                                      const float* __restrict__ Br) {
    const int M = NN, K = 128;
    __shared__ float Bsl[K * 16];
    __shared__ float Bsr[K * 16];
    __shared__ float As[16][K];
    int tid = threadIdx.x;
    int tx = tid % 16, ty = tid / 16;
    for (int i = tid; i < K * 16; i += 256) { Bsl[i] = Bl[i]; Bsr[i] = Br[i]; }
    int r = blockIdx.x * 16 + ty;
#pragma unroll
    for (int i = 0; i < 8; i++) {
        int c = tx + 16 * i;
        As[ty][c] = (r < M) ? g_h1[(size_t)r * K + c] : 0.f;
    }
    __syncthreads();
    unsigned long long acc = 0ull;   // {accl, accr}
#pragma unroll 8
    for (int k = 0; k < K; k++) {
        float a = As[ty][k];
        acc = fma2(pack2(a, a), pack2(Bsl[k * 16 + tx], Bsr[k * 16 + tx]), acc);
    }
    if (r < M) {
        float vl, vr;
        unpack2(acc, vl, vr);
        g_xl2[(size_t)r * 16 + tx] = vl;
        g_xr2[(size_t)r * 16 + tx] = vr;
    }
}

// ---------------- edge scores layer 1: warp per CSR position ----------------------
__global__ void edge_scores1_kernel(const float* __restrict__ att) {
    int w = blockIdx.x * (blockDim.x >> 5) + (threadIdx.x >> 5);
    if (w >= NE) return;
    int lane = threadIdx.x & 31;
    int s = g_srcc[w], d = g_dstc[w];
    float4 a = *(const float4*)(g_xl1 + (size_t)s * D1 + lane * 4);
    float4 b = *(const float4*)(g_xr1 + (size_t)d * D1 + lane * 4);
    float4 t = __ldg((const float4*)att + lane);
    float vx = a.x + b.x; vx = (vx > 0.f) ? vx : NEG_SLOPE * vx;
    float vy = a.y + b.y; vy = (vy > 0.f) ? vy : NEG_SLOPE * vy;
    float vz = a.z + b.z; vz = (vz > 0.f) ? vz : NEG_SLOPE * vz;
    float vw = a.w + b.w; vw = (vw > 0.f) ? vw : NEG_SLOPE * vw;
    float p = vx * t.x + vy * t.y + vz * t.z + vw * t.w;
    p += __shfl_xor_sync(0xffffffffu, p, 1);
    p += __shfl_xor_sync(0xffffffffu, p, 2);
    p += __shfl_xor_sync(0xffffffffu, p, 4);
    if ((lane & 7) == 0) g_scores1[(size_t)w * HEADS + (lane >> 3)] = p;
}

// ---------------- edge scores layer 2: warp handles 8 CSR positions ---------------
__global__ void edge_scores2_kernel(const float* __restrict__ att) {
    int w = blockIdx.x * (blockDim.x >> 5) + (threadIdx.x >> 5);
    int lane = threadIdx.x & 31;
    int sub = lane >> 2;
    int i = lane & 3;
    int e = w * 8 + sub;
    float p = 0.f;
    if (e < NE) {
        int s = g_srcc[e], d = g_dstc[e];
        float4 a = *(const float4*)(g_xl2 + (size_t)s * NCLS + i * 4);
        float4 b = *(const float4*)(g_xr2 + (size_t)d * NCLS + i * 4);
        float4 t = __ldg((const float4*)att + i);
        float vx = a.x + b.x; vx = (vx > 0.f) ? vx : NEG_SLOPE * vx;
        float vy = a.y + b.y; vy = (vy > 0.f) ? vy : NEG_SLOPE * vy;
        float vz = a.z + b.z; vz = (vz > 0.f) ? vz : NEG_SLOPE * vz;
        float vw = a.w + b.w; vw = (vw > 0.f) ? vw : NEG_SLOPE * vw;
        p = vx * t.x + vy * t.y + vz * t.z + vw * t.w;
    }
    p += __shfl_xor_sync(0xffffffffu, p, 1);
    p += __shfl_xor_sync(0xffffffffu, p, 2);
    if (i == 0 && e < NE) g_scores2[e] = p;
}

// ---------------- top-k stats: branchless register list, single pass --------------
template <int KM>
__device__ __forceinline__ void topk_core(const float* __restrict__ scores,
                                          float* __restrict__ stats,
                                          int H, int h, int t, int beg, int cnt, int k) {
    float ts[KM];
    int   te[KM];
#pragma unroll
    for (int i = 0; i < KM; i++) { ts[i] = NEG_INF; te[i] = 0x7fffffff; }

    float mn = NEG_INF;
    float sn = 0.f;

    for (int p = 0; p < cnt; p++) {
        int idx = beg + p;
        float s = scores[(size_t)idx * H + h];
        int e = g_eid[idx];
        bool beats_tail = (s > ts[KM - 1]) || (s == ts[KM - 1] && e < te[KM - 1]);
        float rej;
        if (beats_tail) {
            rej = ts[KM - 1];
            bool nb[KM];
#pragma unroll
            for (int i = 0; i < KM; i++)
                nb[i] = (s > ts[i]) || (s == ts[i] && e < te[i]);
#pragma unroll
            for (int i = KM - 1; i >= 1; i--)
                if (nb[i - 1]) { ts[i] = ts[i - 1]; te[i] = te[i - 1]; }
#pragma unroll
            for (int i = 0; i < KM; i++) {
                bool ins = nb[i] && (i == 0 || !nb[i - 1]);
                if (ins) { ts[i] = s; te[i] = e; }
            }
        } else {
            rej = s;
        }
        if (rej > SENT_LO) {
            if (rej <= mn) sn += __expf(rej - mn);
            else { sn = sn * __expf(mn - rej) + 1.f; mn = rej; }
        }
    }

    int m = min(cnt, KM);
#pragma unroll
    for (int i = 0; i < KM; i++) {
        if (i >= k && i < m && ts[i] > SENT_LO) {
            float v = ts[i];
            if (v <= mn) sn += __expf(v - mn);
            else { sn = sn * __expf(mn - v) + 1.f; mn = v; }
        }
    }

    bool all_kept = (cnt <= k);
    float thr_s = __int_as_float(0x7f800000);
    int   thr_e = -1;
#pragma unroll
    for (int i = 0; i < KM; i++)
        if (i == k - 1) { thr_s = ts[i]; thr_e = te[i]; }

    float mk = (k > 0) ? ts[0] : 0.f;
    float sumk = 0.f;
#pragma unroll
    for (int i = 0; i < KM; i++)
        if (i < k && ts[i] > SENT_LO) sumk += __expf(ts[i] - mk);

    if (mn <= SENT_LO) mn = 0.f;
    float invk = 1.f / (sumk + 1e-16f);
    float invn = 1.f / (sn + 1e-16f);

    float4 s0 = make_float4(thr_s, __int_as_float(thr_e), mk, invk);
    float4 s1 = make_float4(mn, invn, all_kept ? 1.f : 0.f, 0.f);
    *(float4*)&stats[(size_t)t * 8]     = s0;
    *(float4*)&stats[(size_t)t * 8 + 4] = s1;
}

__global__ void topk_stats_kernel(int layer, const int* __restrict__ kptr) {
    const int H = (layer == 1) ? HEADS : 1;
    const float* scores = (layer == 1) ? (const float*)g_scores1 : (const float*)g_scores2;
    float* stats = (layer == 1) ? g_stats1 : g_stats2;

    int t = blockIdx.x * blockDim.x + threadIdx.x;
    if (t >= NN * H) return;
    int n = t / H, h = t - n * H;
    int beg = g_offs[n], cnt = g_counts[n];
    if (cnt == 0) return;
    int k = *kptr;
    k = min(max(k, 0), KMAX);

    if (k <= 8) topk_core<8>(scores, stats, H, h, t, beg, cnt, k);
    else        topk_core<16>(scores, stats, H, h, t, beg, cnt, k);
}

// ---------------- aggregation layer 1: warp per (node, head) ----------------------
__global__ void aggregate1_kernel(const float* __restrict__ b1) {
    int w = blockIdx.x * (blockDim.x >> 5) + (threadIdx.x >> 5);
    if (w >= NN * HEADS) return;
    int lane = threadIdx.x & 31;
    int n = w >> 2, h = w & 3;
    int beg = g_offs[n], cnt = g_counts[n];
    float acc = 0.f, accn = 0.f;
    if (cnt > 0) {
        float4 s0 = *(const float4*)&g_stats1[(size_t)w * 8];
        float4 s1 = *(const float4*)&g_stats1[(size_t)w * 8 + 4];
        float thr_s = s0.x, mk = s0.z, invk = s0.w, mn = s1.x, invn = s1.y;
        int thr_e = __float_as_int(s0.y);
        bool all_kept = (s1.z != 0.f);
        for (int p0 = 0; p0 < cnt; p0 += 32) {
            int p = p0 + lane;
            float a = 0.f, an = 0.f;
            int src = 0;
            if (p < cnt) {
                int idx = beg + p;
                float s = g_scores1[(size_t)idx * HEADS + h];
                int e = g_eid[idx];
                src = g_srcc[idx];
                bool kept = all_kept || (s > thr_s) || (s == thr_s && e <= thr_e);
                float ex = __expf(s - (kept ? mk : mn));
                a  = kept ? ex * invk : 0.f;
                an = kept ? 0.f : ex * invn;
            }
            int lim = min(32, cnt - p0);
            for (int j = 0; j < lim; j++) {
                float aj  = __shfl_sync(0xffffffffu, a, j);
                float anj = __shfl_sync(0xffffffffu, an, j);
                int   sj  = __shfl_sync(0xffffffffu, src, j);
                float xv = g_xl1[(size_t)sj * D1 + h * 32 + lane];
                acc  += aj * xv;
                accn += anj * xv;
            }
        }
    }
    int c = h * 32 + lane;
    float bb = b1[c];
    float o = acc + bb;
    g_h1[(size_t)n * D1 + c]     = (o > 0.f) ? o : expm1f(o);
    g_noise1[(size_t)n * D1 + c] = accn + bb;
}

// ---------------- aggregation layer 2: half-warp per node, lane = class ------------
__global__ void aggregate2_kernel(const float* __restrict__ b2) {
    int w = blockIdx.x * (blockDim.x >> 5) + (threadIdx.x >> 5);
    int lane = threadIdx.x & 31;
    int sub = lane >> 4;
    int c = lane & 15;
    int n = w * 2 + sub;
    if (n >= NN) return;
    int beg = g_offs[n], cnt = g_counts[n];
    float acc = 0.f, accn = 0.f;
    if (cnt > 0) {
        float4 s0 = *(const float4*)&g_stats2[(size_t)n * 8];
        float4 s1 = *(const float4*)&g_stats2[(size_t)n * 8 + 4];
        float thr_s = s0.x, mk = s0.z, invk = s0.w, mn = s1.x, invn = s1.y;
        int thr_e = __float_as_int(s0.y);
        bool all_kept = (s1.z != 0.f);
        for (int p0 = 0; p0 < cnt; p0 += 16) {
            int p = p0 + c;
            float a = 0.f, an = 0.f;
            int src = 0;
            if (p < cnt) {
                int idx = beg + p;
                float s = g_scores2[idx];
                int e = g_eid[idx];
                src = g_srcc[idx];
                bool kept = all_kept || (s > thr_s) || (s == thr_s && e <= thr_e);
                float ex = __expf(s - (kept ? mk : mn));
                a  = kept ? ex * invk : 0.f;
                an = kept ? 0.f : ex * invn;
            }
            int lim = min(16, cnt - p0);
            int base = sub << 4;
            for (int j = 0; j < lim; j++) {
                float aj  = __shfl_sync(0xffffffffu, a, base + j);
                float anj = __shfl_sync(0xffffffffu, an, base + j);
                int   sj  = __shfl_sync(0xffffffffu, src, base + j);
                float xv = g_xl2[(size_t)sj * NCLS + c];
                acc  += aj * xv;
                accn += anj * xv;
            }
        }
    }
    float bb = b2[c];
    g_out2[(size_t)n * NCLS + c]   = acc + bb;
    g_noise2[(size_t)n * NCLS + c] = accn + bb;
}

// ---------------- log_softmax over 16 classes, thread per row, 3 inputs ------------
__global__ void log_softmax16_kernel(float* __restrict__ out) {
    int r = blockIdx.x * blockDim.x + threadIdx.x;
    if (r >= 3 * NN) return;
    const float* in = (r < NN) ? (const float*)g_out2
                    : (r < 2 * NN) ? (const float*)g_n1 - (size_t)NN * NCLS
                    : (const float*)g_noise2 - 2 * (size_t)NN * NCLS;
    float v[NCLS];
    float mx = -3.4e38f;
#pragma unroll
    for (int c = 0; c < NCLS; c++) { v[c] = in[(size_t)r * NCLS + c]; mx = fmaxf(mx, v[c]); }
    float s = 0.f;
#pragma unroll
    for (int c = 0; c < NCLS; c++) s += __expf(v[c] - mx);
    float ls = mx + __logf(s);
#pragma unroll
    for (int c = 0; c < NCLS; c++) out[(size_t)r * NCLS + c] = v[c] - ls;
}

// ---------------- host ----------------
extern "C" void kernel_launch(void* const* d_in, const int* in_sizes, int n_in,
                              void* d_out, int out_size) {
    const float* x      = (const float*)d_in[0];
    const int*   ei     = (const int*)d_in[1];
    const int*   kptr   = (const int*)d_in[2];
    const float* Wl1    = (const float*)d_in[3];
    const float* Wr1    = (const float*)d_in[4];
    const float* att1   = (const float*)d_in[5];
    const float* b1     = (const float*)d_in[6];
    const float* Wl2    = (const float*)d_in[7];
    const float* Wr2    = (const float*)d_in[8];
    const float* att2   = (const float*)d_in[9];
    const float* b2     = (const float*)d_in[10];
    const float* lin1_w = (const float*)d_in[11];
    const float* lin1_b = (const float*)d_in[12];
    const float* lin2_w = (const float*)d_in[13];
    const float* lin2_b = (const float*)d_in[14];
    float* out = (float*)d_out;

    // Side stream + events: created ONCE on the first (uncaptured) correctness
    // call; on the captured call they express fork/join graph dependencies.
    static cudaStream_t s1 = nullptr;
    static cudaEvent_t ev_root = nullptr, ev_csr = nullptr, ev_agg = nullptr, ev_n1 = nullptr;
    if (s1 == nullptr) {
        cudaStreamCreateWithFlags(&s1, cudaStreamNonBlocking);
        cudaEventCreateWithFlags(&ev_root, cudaEventDisableTiming);
        cudaEventCreateWithFlags(&ev_csr, cudaEventDisableTiming);
        cudaEventCreateWithFlags(&ev_agg, cudaEventDisableTiming);
        cudaEventCreateWithFlags(&ev_n1, cudaEventDisableTiming);
    }

    dim3 gProj((NN + 127) / 128, 2);
    dim3 gMlp((NN + 127) / 128, 1);

    // ---- fork: CSR build on s1 runs concurrently with projection GEMM on main ----
    cudaEventRecord(ev_root, 0);
    cudaStreamWaitEvent(s1, ev_root, 0);

    init_csr_kernel<<<(NN + 255) / 256, 256, 0, s1>>>();
    count_kernel<<<(NE + 255) / 256, 256, 0, s1>>>(ei);
    block_sum_kernel<<<NBLK_SCAN, 256, 0, s1>>>();
    scan_partials_kernel<<<1, 256, 0, s1>>>();
    scan_final_kernel<<<NBLK_SCAN, 256, 0, s1>>>();
    scatter_kernel<<<(NE + 255) / 256, 256, 0, s1>>>(ei);
    cudaEventRecord(ev_csr, s1);

    sgemm128_kernel<<<gProj, 256>>>(0, x, Wl1, Wr1, nullptr, 0);   // main stream

    // ---- join: layer-1 attention needs both ----
    cudaStreamWaitEvent(0, ev_csr, 0);
    edge_scores1_kernel<<<(NE + 7) / 8, 256>>>(att1);
    topk_stats_kernel<<<(NN * HEADS + 255) / 256, 256>>>(1, kptr);
    aggregate1_kernel<<<(NN * HEADS + 7) / 8, 256>>>(b1);
    cudaEventRecord(ev_agg, 0);

    // ---- fork: noise-MLP path on s1, layer-2 path on main ----
    cudaStreamWaitEvent(s1, ev_agg, 0);
    sgemm128_kernel<<<gMlp, 256, 0, s1>>>(2, nullptr, lin1_w, nullptr, lin1_b, 1);
    sgemm_n16_kernel<<<(NN + 31) / 32, 256, 0, s1>>>(lin2_w, lin2_b);
    cudaEventRecord(ev_n1, s1);

    sgemm_n16_dual_kernel<<<(NN + 15) / 16, 256>>>(Wl2, Wr2);
    edge_scores2_kernel<<<((NE + 7) / 8 + 7) / 8, 256>>>(att2);
    topk_stats_kernel<<<(NN + 255) / 256, 256>>>(2, kptr);
    aggregate2_kernel<<<((NN + 1) / 2 + 7) / 8, 256>>>(b2);

    // ---- join: outputs need both paths ----
    cudaStreamWaitEvent(0, ev_n1, 0);
    log_softmax16_kernel<<<(3 * NN + 255) / 256, 256>>>(out);
}

// round 17
// speedup vs baseline: 1.1320x; 1.0580x over previous
#include <cuda_runtime.h>
#include <math.h>
#include <stdint.h>

#define NN    50000
#define NE    800000
#define FIN   128
#define HID   32
#define HEADS 4
#define D1    128      // HEADS*HID
#define NCLS  16
#define MLPH  128
#define KMAX  16
#define NEG_SLOPE 0.2f
#define NBLK_SCAN 196  // ceil(NN/256)
#define NEG_INF  (-__int_as_float(0x7f800000))
#define SENT_LO  (-1e37f)

// ---------------- packed f32x2 helpers (sm_103 FFMA2 path) ----------------
__device__ __forceinline__ unsigned long long pack2(float x, float y) {
    unsigned long long r;
    asm("mov.b64 %0, {%1, %2};" : "=l"(r) : "f"(x), "f"(y));
    return r;
}
__device__ __forceinline__ void unpack2(unsigned long long v, float& x, float& y) {
    asm("mov.b64 {%0, %1}, %2;" : "=f"(x), "=f"(y) : "l"(v));
}
__device__ __forceinline__ unsigned long long fma2(unsigned long long a,
                                                   unsigned long long b,
                                                   unsigned long long c) {
    unsigned long long d;
    asm("fma.rn.f32x2 %0, %1, %2, %3;" : "=l"(d) : "l"(a), "l"(b), "l"(c));
    return d;
}

// ---------------- scratch (static device memory; no runtime allocs) ----------------
__device__ int   g_eid[NE];
__device__ int   g_srcc[NE];
__device__ int   g_dstc[NE];
__device__ int   g_counts[NN], g_offs[NN], g_cursor[NN];
__device__ int   g_blocksum[NBLK_SCAN], g_blockbase[NBLK_SCAN];
__device__ __align__(16) float g_xl1[(size_t)NN * D1];
__device__ __align__(16) float g_xr1[(size_t)NN * D1];
__device__ __align__(16) float g_scores1[(size_t)NE * HEADS];   // CSR order [pos][h]
__device__ __align__(16) float g_stats1[(size_t)NN * HEADS * 8];
__device__ __align__(16) float g_stats2[(size_t)NN * 8];
__device__ __align__(16) float g_h1[(size_t)NN * D1];
__device__ __align__(16) float g_noise1[(size_t)NN * D1];
__device__ __align__(16) float g_mlph[(size_t)NN * MLPH];
__device__ __align__(16) float g_xl2[NN * NCLS];
__device__ __align__(16) float g_xr2[NN * NCLS];
__device__ __align__(16) float g_scores2[NE];

// ---------------- CSR build ----------------
__global__ void init_csr_kernel() {
    int i = blockIdx.x * blockDim.x + threadIdx.x;
    if (i < NN) { g_counts[i] = 0; g_cursor[i] = 0; }
}

__global__ void count_kernel(const int* __restrict__ ei) {
    int e = blockIdx.x * blockDim.x + threadIdx.x;
    if (e < NE) {
        int d = min(max(ei[NE + e], 0), NN - 1);
        atomicAdd(&g_counts[d], 1);
    }
}

__global__ void block_sum_kernel() {
    __shared__ int sh[256];
    int b = blockIdx.x, t = threadIdx.x;
    int i = b * 256 + t;
    sh[t] = (i < NN) ? g_counts[i] : 0;
    __syncthreads();
    for (int o = 128; o > 0; o >>= 1) {
        if (t < o) sh[t] += sh[t + o];
        __syncthreads();
    }
    if (t == 0) g_blocksum[b] = sh[0];
}

__global__ void scan_partials_kernel() {
    __shared__ int sh[256];
    int t = threadIdx.x;
    int v = (t < NBLK_SCAN) ? g_blocksum[t] : 0;
    sh[t] = v;
    __syncthreads();
    for (int o = 1; o < 256; o <<= 1) {
        int u = (t >= o) ? sh[t - o] : 0;
        __syncthreads();
        sh[t] += u;
        __syncthreads();
    }
    if (t < NBLK_SCAN) g_blockbase[t] = sh[t] - v;
}

__global__ void scan_final_kernel() {
    __shared__ int sh[256];
    int b = blockIdx.x, t = threadIdx.x;
    int i = b * 256 + t;
    int v = (i < NN) ? g_counts[i] : 0;
    sh[t] = v;
    __syncthreads();
    for (int o = 1; o < 256; o <<= 1) {
        int u = (t >= o) ? sh[t - o] : 0;
        __syncthreads();
        sh[t] += u;
        __syncthreads();
    }
    if (i < NN) g_offs[i] = g_blockbase[b] + sh[t] - v;
}

__global__ void scatter_kernel(const int* __restrict__ ei) {
    int e = blockIdx.x * blockDim.x + threadIdx.x;
    if (e < NE) {
        int s = min(max(ei[e], 0), NN - 1);
        int d = min(max(ei[NE + e], 0), NN - 1);
        int pos = g_offs[d] + atomicAdd(&g_cursor[d], 1);
        g_eid[pos] = e;
        g_srcc[pos] = s;
        g_dstc[pos] = d;
    }
}

// ---------------- SGEMM: 128x128 tile, 8x8 microtile, FFMA2 inner loop ------------
__global__ void sgemm128_kernel(int tag, const float* __restrict__ Aparam,
                                const float* __restrict__ B1,
                                const float* __restrict__ B2,
                                const float* __restrict__ bias, int act) {
    const int M = NN, N = 128, K = 128;
    const int BK = 16;
    __shared__ float As[BK][128 + 4];
    __shared__ float Bs[BK][128];
    const float* A = (tag == 2) ? (const float*)g_noise1 : Aparam;
    const float* B = (tag == 0 && blockIdx.y == 1) ? B2 : B1;
    float* C = (tag == 2) ? g_mlph : (blockIdx.y == 0 ? g_xl1 : g_xr1);

    int row0 = blockIdx.x * 128;
    int tid = threadIdx.x;
    int tx = tid % 16, ty = tid / 16;
    int lr = tid / 16, lc = tid % 16;
    int bc = tid % 128, br0 = tid / 128;
    unsigned long long acc2[8][4];
#pragma unroll
    for (int i = 0; i < 8; i++)
#pragma unroll
        for (int j = 0; j < 4; j++) acc2[i][j] = 0ull;

    for (int k0 = 0; k0 < K; k0 += BK) {
#pragma unroll
        for (int i = 0; i < 8; i++) {
            int r = row0 + lr + 16 * i;
            float v = 0.f;
            if (r < M) v = A[(size_t)r * K + k0 + lc];
            As[lc][lr + 16 * i] = v;
        }
#pragma unroll
        for (int i = 0; i < 8; i++) {
            int kr = k0 + br0 + 2 * i;
            Bs[br0 + 2 * i][bc] = B[(size_t)kr * N + bc];
        }
        __syncthreads();
#pragma unroll
        for (int kk = 0; kk < BK; kk++) {
            float4 a0 = *(const float4*)&As[kk][ty * 8];
            float4 a1 = *(const float4*)&As[kk][ty * 8 + 4];
            float4 b0 = *(const float4*)&Bs[kk][tx * 8];
            float4 b1 = *(const float4*)&Bs[kk][tx * 8 + 4];
            unsigned long long bp[4];
            bp[0] = pack2(b0.x, b0.y);
            bp[1] = pack2(b0.z, b0.w);
            bp[2] = pack2(b1.x, b1.y);
            bp[3] = pack2(b1.z, b1.w);
            unsigned long long ap[8];
            ap[0] = pack2(a0.x, a0.x);
            ap[1] = pack2(a0.y, a0.y);
            ap[2] = pack2(a0.z, a0.z);
            ap[3] = pack2(a0.w, a0.w);
            ap[4] = pack2(a1.x, a1.x);
            ap[5] = pack2(a1.y, a1.y);
            ap[6] = pack2(a1.z, a1.z);
            ap[7] = pack2(a1.w, a1.w);
#pragma unroll
            for (int i = 0; i < 8; i++)
#pragma unroll
                for (int j = 0; j < 4; j++)
                    acc2[i][j] = fma2(ap[i], bp[j], acc2[i][j]);
        }
        __syncthreads();
    }
#pragma unroll
    for (int i = 0; i < 8; i++) {
        int r = row0 + ty * 8 + i;
        if (r >= M) continue;
#pragma unroll
        for (int j = 0; j < 4; j++) {
            float vlo, vhi;
            unpack2(acc2[i][j], vlo, vhi);
            int c = tx * 8 + j * 2;
            if (bias) { vlo += bias[c]; vhi += bias[c + 1]; }
            if (act == 1) {
                vlo = (vlo > 0.f) ? vlo : expm1f(vlo);
                vhi = (vhi > 0.f) ? vhi : expm1f(vhi);
            }
            C[(size_t)r * N + c]     = vlo;
            C[(size_t)r * N + c + 1] = vhi;
        }
    }
}

// N=16 GEMM + fused log_softmax: out_n1 = log_softmax(g_mlph @ B + bias)
// 256 threads = 32 rows x 8 column-pairs. All lanes converged at the shfls
// (no early returns before them); xor o<8 stays inside each 8-lane row group.
__global__ void sgemm_n16_ls_kernel(const float* __restrict__ B,
                                    const float* __restrict__ bias,
                                    float* __restrict__ outp) {
    const int M = NN, K = 128;
    __shared__ float Bs[K * 16];
    __shared__ float As[32][K];
    int tid = threadIdx.x;
    int tx = tid % 8, ty = tid / 8;
    for (int i = tid; i < K * 16; i += 256) Bs[i] = B[i];
    int r = blockIdx.x * 32 + ty;
#pragma unroll
    for (int i = 0; i < 16; i++) {
        int c = tx + 8 * i;
        As[ty][c] = (r < M) ? g_mlph[(size_t)r * K + c] : 0.f;
    }
    __syncthreads();
    unsigned long long acc = 0ull;
#pragma unroll 8
    for (int k = 0; k < K; k++) {
        float a = As[ty][k];
        acc = fma2(pack2(a, a), pack2(Bs[k * 16 + tx], Bs[k * 16 + tx + 8]), acc);
    }
    float v0, v1;
    unpack2(acc, v0, v1);
    v0 += bias[tx];
    v1 += bias[tx + 8];
    float mx = fmaxf(v0, v1);
#pragma unroll
    for (int o = 1; o < 8; o <<= 1) mx = fmaxf(mx, __shfl_xor_sync(0xffffffffu, mx, o));
    float s = __expf(v0 - mx) + __expf(v1 - mx);
#pragma unroll
    for (int o = 1; o < 8; o <<= 1) s += __shfl_xor_sync(0xffffffffu, s, o);
    float ls = mx + __logf(s);
    if (r < M) {
        outp[(size_t)r * 16 + tx]     = v0 - ls;
        outp[(size_t)r * 16 + tx + 8] = v1 - ls;
    }
}

// dual N=16 GEMM (FFMA2 l/r pairs): xl2 = h1 @ Wl2, xr2 = h1 @ Wr2
__global__ void sgemm_n16_dual_kernel(const float* __restrict__ Bl,
                                      const float* __restrict__ Br) {
    const int M = NN, K = 128;
    __shared__ float Bsl[K * 16];
    __shared__ float Bsr[K * 16];
    __shared__ float As[16][K];
    int tid = threadIdx.x;
    int tx = tid % 16, ty = tid / 16;
    for (int i = tid; i < K * 16; i += 256) { Bsl[i] = Bl[i]; Bsr[i] = Br[i]; }
    int r = blockIdx.x * 16 + ty;
#pragma unroll
    for (int i = 0; i < 8; i++) {
        int c = tx + 16 * i;
        As[ty][c] = (r < M) ? g_h1[(size_t)r * K + c] : 0.f;
    }
    __syncthreads();
    unsigned long long acc = 0ull;   // {accl, accr}
#pragma unroll 8
    for (int k = 0; k < K; k++) {
        float a = As[ty][k];
        acc = fma2(pack2(a, a), pack2(Bsl[k * 16 + tx], Bsr[k * 16 + tx]), acc);
    }
    if (r < M) {
        float vl, vr;
        unpack2(acc, vl, vr);
        g_xl2[(size_t)r * 16 + tx] = vl;
        g_xr2[(size_t)r * 16 + tx] = vr;
    }
}

// ---------------- edge scores layer 1: warp per CSR position ----------------------
__global__ void edge_scores1_kernel(const float* __restrict__ att) {
    int w = blockIdx.x * (blockDim.x >> 5) + (threadIdx.x >> 5);
    if (w >= NE) return;
    int lane = threadIdx.x & 31;
    int s = g_srcc[w], d = g_dstc[w];
    float4 a = *(const float4*)(g_xl1 + (size_t)s * D1 + lane * 4);
    float4 b = *(const float4*)(g_xr1 + (size_t)d * D1 + lane * 4);
    float4 t = __ldg((const float4*)att + lane);
    float vx = a.x + b.x; vx = (vx > 0.f) ? vx : NEG_SLOPE * vx;
    float vy = a.y + b.y; vy = (vy > 0.f) ? vy : NEG_SLOPE * vy;
    float vz = a.z + b.z; vz = (vz > 0.f) ? vz : NEG_SLOPE * vz;
    float vw = a.w + b.w; vw = (vw > 0.f) ? vw : NEG_SLOPE * vw;
    float p = vx * t.x + vy * t.y + vz * t.z + vw * t.w;
    p += __shfl_xor_sync(0xffffffffu, p, 1);
    p += __shfl_xor_sync(0xffffffffu, p, 2);
    p += __shfl_xor_sync(0xffffffffu, p, 4);
    if ((lane & 7) == 0) g_scores1[(size_t)w * HEADS + (lane >> 3)] = p;
}

// ---------------- edge scores layer 2: warp handles 8 CSR positions ---------------
__global__ void edge_scores2_kernel(const float* __restrict__ att) {
    int w = blockIdx.x * (blockDim.x >> 5) + (threadIdx.x >> 5);
    int lane = threadIdx.x & 31;
    int sub = lane >> 2;
    int i = lane & 3;
    int e = w * 8 + sub;
    float p = 0.f;
    if (e < NE) {
        int s = g_srcc[e], d = g_dstc[e];
        float4 a = *(const float4*)(g_xl2 + (size_t)s * NCLS + i * 4);
        float4 b = *(const float4*)(g_xr2 + (size_t)d * NCLS + i * 4);
        float4 t = __ldg((const float4*)att + i);
        float vx = a.x + b.x; vx = (vx > 0.f) ? vx : NEG_SLOPE * vx;
        float vy = a.y + b.y; vy = (vy > 0.f) ? vy : NEG_SLOPE * vy;
        float vz = a.z + b.z; vz = (vz > 0.f) ? vz : NEG_SLOPE * vz;
        float vw = a.w + b.w; vw = (vw > 0.f) ? vw : NEG_SLOPE * vw;
        p = vx * t.x + vy * t.y + vz * t.z + vw * t.w;
    }
    p += __shfl_xor_sync(0xffffffffu, p, 1);
    p += __shfl_xor_sync(0xffffffffu, p, 2);
    if (i == 0 && e < NE) g_scores2[e] = p;
}

// ---------------- top-k stats: branchless register list, single pass --------------
template <int KM>
__device__ __forceinline__ void topk_core(const float* __restrict__ scores,
                                          float* __restrict__ stats,
                                          int H, int h, int t, int beg, int cnt, int k) {
    float ts[KM];
    int   te[KM];
#pragma unroll
    for (int i = 0; i < KM; i++) { ts[i] = NEG_INF; te[i] = 0x7fffffff; }

    float mn = NEG_INF;
    float sn = 0.f;

    for (int p = 0; p < cnt; p++) {
        int idx = beg + p;
        float s = scores[(size_t)idx * H + h];
        int e = g_eid[idx];
        bool beats_tail = (s > ts[KM - 1]) || (s == ts[KM - 1] && e < te[KM - 1]);
        float rej;
        if (beats_tail) {
            rej = ts[KM - 1];
            bool nb[KM];
#pragma unroll
            for (int i = 0; i < KM; i++)
                nb[i] = (s > ts[i]) || (s == ts[i] && e < te[i]);
#pragma unroll
            for (int i = KM - 1; i >= 1; i--)
                if (nb[i - 1]) { ts[i] = ts[i - 1]; te[i] = te[i - 1]; }
#pragma unroll
            for (int i = 0; i < KM; i++) {
                bool ins = nb[i] && (i == 0 || !nb[i - 1]);
                if (ins) { ts[i] = s; te[i] = e; }
            }
        } else {
            rej = s;
        }
        if (rej > SENT_LO) {
            if (rej <= mn) sn += __expf(rej - mn);
            else { sn = sn * __expf(mn - rej) + 1.f; mn = rej; }
        }
    }

    int m = min(cnt, KM);
#pragma unroll
    for (int i = 0; i < KM; i++) {
        if (i >= k && i < m && ts[i] > SENT_LO) {
            float v = ts[i];
            if (v <= mn) sn += __expf(v - mn);
            else { sn = sn * __expf(mn - v) + 1.f; mn = v; }
        }
    }

    bool all_kept = (cnt <= k);
    float thr_s = __int_as_float(0x7f800000);
    int   thr_e = -1;
#pragma unroll
    for (int i = 0; i < KM; i++)
        if (i == k - 1) { thr_s = ts[i]; thr_e = te[i]; }

    float mk = (k > 0) ? ts[0] : 0.f;
    float sumk = 0.f;
#pragma unroll
    for (int i = 0; i < KM; i++)
        if (i < k && ts[i] > SENT_LO) sumk += __expf(ts[i] - mk);

    if (mn <= SENT_LO) mn = 0.f;
    float invk = 1.f / (sumk + 1e-16f);
    float invn = 1.f / (sn + 1e-16f);

    float4 s0 = make_float4(thr_s, __int_as_float(thr_e), mk, invk);
    float4 s1 = make_float4(mn, invn, all_kept ? 1.f : 0.f, 0.f);
    *(float4*)&stats[(size_t)t * 8]     = s0;
    *(float4*)&stats[(size_t)t * 8 + 4] = s1;
}

__global__ void topk_stats_kernel(int layer, const int* __restrict__ kptr) {
    const int H = (layer == 1) ? HEADS : 1;
    const float* scores = (layer == 1) ? (const float*)g_scores1 : (const float*)g_scores2;
    float* stats = (layer == 1) ? g_stats1 : g_stats2;

    int t = blockIdx.x * blockDim.x + threadIdx.x;
    if (t >= NN * H) return;
    int n = t / H, h = t - n * H;
    int beg = g_offs[n], cnt = g_counts[n];
    if (cnt == 0) return;
    int k = *kptr;
    k = min(max(k, 0), KMAX);

    if (k <= 8) topk_core<8>(scores, stats, H, h, t, beg, cnt, k);
    else        topk_core<16>(scores, stats, H, h, t, beg, cnt, k);
}

// ---------------- aggregation layer 1: warp per (node, head) ----------------------
// All 32 lanes share (n,h): fully converged at every shfl (full mask safe).
__global__ void aggregate1_kernel(const float* __restrict__ b1) {
    int w = blockIdx.x * (blockDim.x >> 5) + (threadIdx.x >> 5);
    if (w >= NN * HEADS) return;
    int lane = threadIdx.x & 31;
    int n = w >> 2, h = w & 3;
    int beg = g_offs[n], cnt = g_counts[n];
    float acc = 0.f, accn = 0.f;
    if (cnt > 0) {
        float4 s0 = *(const float4*)&g_stats1[(size_t)w * 8];
        float4 s1 = *(const float4*)&g_stats1[(size_t)w * 8 + 4];
        float thr_s = s0.x, mk = s0.z, invk = s0.w, mn = s1.x, invn = s1.y;
        int thr_e = __float_as_int(s0.y);
        bool all_kept = (s1.z != 0.f);
        for (int p0 = 0; p0 < cnt; p0 += 32) {
            int p = p0 + lane;
            float a = 0.f, an = 0.f;
            int src = 0;
            if (p < cnt) {
                int idx = beg + p;
                float s = g_scores1[(size_t)idx * HEADS + h];
                int e = g_eid[idx];
                src = g_srcc[idx];
                bool kept = all_kept || (s > thr_s) || (s == thr_s && e <= thr_e);
                float ex = __expf(s - (kept ? mk : mn));
                a  = kept ? ex * invk : 0.f;
                an = kept ? 0.f : ex * invn;
            }
            int lim = min(32, cnt - p0);
            for (int j = 0; j < lim; j++) {
                float aj  = __shfl_sync(0xffffffffu, a, j);
                float anj = __shfl_sync(0xffffffffu, an, j);
                int   sj  = __shfl_sync(0xffffffffu, src, j);
                float xv = g_xl1[(size_t)sj * D1 + h * 32 + lane];
                acc  += aj * xv;
                accn += anj * xv;
            }
        }
    }
    int c = h * 32 + lane;
    float bb = b1[c];
    float o = acc + bb;
    g_h1[(size_t)n * D1 + c]     = (o > 0.f) ? o : expm1f(o);
    g_noise1[(size_t)n * D1 + c] = accn + bb;
}

// ---------------- aggregation layer 2 + fused log_softmax -------------------------
// Half-warp per node. ALL shfls use the half-warp member mask so each half only
// requires its own (always-converged) 16 lanes — the two halves have different
// nodes/trip-counts and may diverge relative to each other.
__global__ void aggregate2_ls_kernel(const float* __restrict__ b2,
                                     float* __restrict__ outp,
                                     float* __restrict__ outn) {
    int w = blockIdx.x * (blockDim.x >> 5) + (threadIdx.x >> 5);
    int lane = threadIdx.x & 31;
    int sub = lane >> 4;
    int c = lane & 15;
    unsigned hmask = 0xFFFFu << (sub << 4);   // this half-warp's member mask
    int n = w * 2 + sub;
    if (n >= NN) return;   // NN even: both halves exit together
    int beg = g_offs[n], cnt = g_counts[n];
    float acc = 0.f, accn = 0.f;
    if (cnt > 0) {
        float4 s0 = *(const float4*)&g_stats2[(size_t)n * 8];
        float4 s1 = *(const float4*)&g_stats2[(size_t)n * 8 + 4];
        float thr_s = s0.x, mk = s0.z, invk = s0.w, mn = s1.x, invn = s1.y;
        int thr_e = __float_as_int(s0.y);
        bool all_kept = (s1.z != 0.f);
        int base = sub << 4;
        for (int p0 = 0; p0 < cnt; p0 += 16) {
            int p = p0 + c;
            float a = 0.f, an = 0.f;
            int src = 0;
            if (p < cnt) {
                int idx = beg + p;
                float s = g_scores2[idx];
                int e = g_eid[idx];
                src = g_srcc[idx];
                bool kept = all_kept || (s > thr_s) || (s == thr_s && e <= thr_e);
                float ex = __expf(s - (kept ? mk : mn));
                a  = kept ? ex * invk : 0.f;
                an = kept ? 0.f : ex * invn;
            }
            int lim = min(16, cnt - p0);
            for (int j = 0; j < lim; j++) {
                float aj  = __shfl_sync(hmask, a, base + j);
                float anj = __shfl_sync(hmask, an, base + j);
                int   sj  = __shfl_sync(hmask, src, base + j);
                float xv = g_xl2[(size_t)sj * NCLS + c];
                acc  += aj * xv;
                accn += anj * xv;
            }
        }
    }
    float bb = b2[c];
    float v  = acc + bb;
    float vn = accn + bb;
    // fused log_softmax over this half's 16 lanes (xor < 16 stays in-half)
    float m1 = v, m2 = vn;
#pragma unroll
    for (int o = 1; o < 16; o <<= 1) {
        m1 = fmaxf(m1, __shfl_xor_sync(hmask, m1, o));
        m2 = fmaxf(m2, __shfl_xor_sync(hmask, m2, o));
    }
    float su1 = __expf(v - m1), su2 = __expf(vn - m2);
#pragma unroll
    for (int o = 1; o < 16; o <<= 1) {
        su1 += __shfl_xor_sync(hmask, su1, o);
        su2 += __shfl_xor_sync(hmask, su2, o);
    }
    outp[(size_t)n * NCLS + c] = v  - (m1 + __logf(su1));
    outn[(size_t)n * NCLS + c] = vn - (m2 + __logf(su2));
}

// ---------------- host ----------------
extern "C" void kernel_launch(void* const* d_in, const int* in_sizes, int n_in,
                              void* d_out, int out_size) {
    const float* x      = (const float*)d_in[0];
    const int*   ei     = (const int*)d_in[1];
    const int*   kptr   = (const int*)d_in[2];
    const float* Wl1    = (const float*)d_in[3];
    const float* Wr1    = (const float*)d_in[4];
    const float* att1   = (const float*)d_in[5];
    const float* b1     = (const float*)d_in[6];
    const float* Wl2    = (const float*)d_in[7];
    const float* Wr2    = (const float*)d_in[8];
    const float* att2   = (const float*)d_in[9];
    const float* b2     = (const float*)d_in[10];
    const float* lin1_w = (const float*)d_in[11];
    const float* lin1_b = (const float*)d_in[12];
    const float* lin2_w = (const float*)d_in[13];
    const float* lin2_b = (const float*)d_in[14];
    float* out = (float*)d_out;

    static cudaStream_t s1 = nullptr;
    static cudaEvent_t ev_root = nullptr, ev_csr = nullptr, ev_agg = nullptr, ev_n1 = nullptr;
    if (s1 == nullptr) {
        cudaStreamCreateWithFlags(&s1, cudaStreamNonBlocking);
        cudaEventCreateWithFlags(&ev_root, cudaEventDisableTiming);
        cudaEventCreateWithFlags(&ev_csr, cudaEventDisableTiming);
        cudaEventCreateWithFlags(&ev_agg, cudaEventDisableTiming);
        cudaEventCreateWithFlags(&ev_n1, cudaEventDisableTiming);
    }

    dim3 gProj((NN + 127) / 128, 2);
    dim3 gMlp((NN + 127) / 128, 1);

    // ---- fork: CSR build on s1 concurrent with projection GEMM on main ----
    cudaEventRecord(ev_root, 0);
    cudaStreamWaitEvent(s1, ev_root, 0);

    init_csr_kernel<<<(NN + 255) / 256, 256, 0, s1>>>();
    count_kernel<<<(NE + 255) / 256, 256, 0, s1>>>(ei);
    block_sum_kernel<<<NBLK_SCAN, 256, 0, s1>>>();
    scan_partials_kernel<<<1, 256, 0, s1>>>();
    scan_final_kernel<<<NBLK_SCAN, 256, 0, s1>>>();
    scatter_kernel<<<(NE + 255) / 256, 256, 0, s1>>>(ei);
    cudaEventRecord(ev_csr, s1);

    sgemm128_kernel<<<gProj, 256>>>(0, x, Wl1, Wr1, nullptr, 0);   // main stream

    // ---- join: layer-1 attention needs both ----
    cudaStreamWaitEvent(0, ev_csr, 0);
    edge_scores1_kernel<<<(NE + 7) / 8, 256>>>(att1);
    topk_stats_kernel<<<(NN * HEADS + 255) / 256, 256>>>(1, kptr);
    aggregate1_kernel<<<(NN * HEADS + 7) / 8, 256>>>(b1);
    cudaEventRecord(ev_agg, 0);

    // ---- fork: noise-MLP path (writes n1 log_softmax directly) on s1 ----
    cudaStreamWaitEvent(s1, ev_agg, 0);
    sgemm128_kernel<<<gMlp, 256, 0, s1>>>(2, nullptr, lin1_w, nullptr, lin1_b, 1);
    sgemm_n16_ls_kernel<<<(NN + 31) / 32, 256, 0, s1>>>(lin2_w, lin2_b,
                                                        out + (size_t)NN * NCLS);
    cudaEventRecord(ev_n1, s1);

    // ---- layer-2 path on main (writes out2/noise2 log_softmax directly) ----
    sgemm_n16_dual_kernel<<<(NN + 15) / 16, 256>>>(Wl2, Wr2);
    edge_scores2_kernel<<<((NE + 7) / 8 + 7) / 8, 256>>>(att2);
    topk_stats_kernel<<<(NN + 255) / 256, 256>>>(2, kptr);
    aggregate2_ls_kernel<<<((NN + 1) / 2 + 7) / 8, 256>>>(b2, out,
                                                          out + 2 * (size_t)NN * NCLS);

    // ---- join s1 back into the capture stream (event edge only) ----
    cudaStreamWaitEvent(0, ev_n1, 0);
}